// round 14
// baseline (speedup 1.0000x reference)
#include <cuda_runtime.h>
#include <cuda_fp16.h>

#define N_NODES 100000
#define N_EDGES 3200000
#define CAP     128          // per-node bucket capacity; max in-degree ~60 for this graph

// ---- persistent device scratch (no allocations allowed) ----
__device__ int   g_cnt[N_NODES];                       // degree / cursor (zeroed by agg3)
__device__ float g_dinv[N_NODES];
__device__ int   g_bucket[(size_t)N_NODES * CAP];      // padded CSR (51.2 MB)
__device__ __align__(16) float  g_bufA[(size_t)N_NODES * 32];  // raw x@W1 (fp32)
__device__ __align__(16) float  g_bufB[(size_t)N_NODES * 32];  // g3 (fp32)
__device__ __align__(16) __half g_h1[(size_t)N_NODES * 32];    // scaled layer-1 feats
__device__ __align__(16) __half g_h2[(size_t)N_NODES * 16];    // scaled layer-2 feats

// dtype check: int64 edge indices < 2^31 have all-zero high (odd) int32 words.
__device__ __forceinline__ int detect_is64(const int* ei32) {
    __shared__ int s_is64;
    if (threadIdx.x < 32) {
        int pos = 2 * (threadIdx.x * 100000) + 1;      // max 6200001 < 6400000
        unsigned m = __ballot_sync(0xffffffffu, ei32[pos] != 0);
        if (threadIdx.x == 0) s_is64 = (m == 0);
    }
    __syncthreads();
    return s_is64;
}

// ---- one-pass bucketed CSR build: p = cnt[d]++; bucket[d*CAP+p] = s ----
__global__ void k_scatter(const int* __restrict__ ei32) {
    int is64 = detect_is64(ei32);
    int e = blockIdx.x * blockDim.x + threadIdx.x;
    if (e >= N_EDGES) return;
    int s, d;
    if (is64) {
        s = ei32[2 * e];
        d = ei32[2 * (N_EDGES + e)];
    } else {
        s = ei32[e];
        d = ei32[N_EDGES + e];
    }
    s = min(max(s, 0), N_NODES - 1);
    d = min(max(d, 0), N_NODES - 1);
    int p = atomicAdd(&g_cnt[d], 1);
    if (p < CAP) g_bucket[(size_t)d * CAP + p] = s;
}

// ---- finish: dinv = rsqrt(deg+1); h1[n][c] = fp16( bufA[n][c] * dinv[n] ) ----
__global__ void k_finish(const float* __restrict__ g) {
    int node = (int)((blockIdx.x * blockDim.x + threadIdx.x) >> 5);
    int lane = threadIdx.x & 31;
    if (node >= N_NODES) return;
    float dn = rsqrtf((float)(g_cnt[node] + 1));
    if (lane == 0) g_dinv[node] = dn;
    g_h1[(size_t)node * 32 + lane] = __float2half(g[(size_t)node * 32 + lane] * dn);
}

// ---- layer-1 GEMM: 128 -> 32, raw fp32 (no deps -> overlaps scatter) ----
__global__ void k_gemm1(const float* __restrict__ x, const float* __restrict__ W,
                        float* __restrict__ g) {
    __shared__ float Xs[32 * 128];
    __shared__ float Ws[128 * 32];
    int tid = threadIdx.x;
    int nb = blockIdx.x * 32;

    const float4* W4 = (const float4*)W;
    float4* Ws4 = (float4*)Ws;
    for (int i = tid; i < 1024; i += 256) Ws4[i] = W4[i];
    const float4* X4 = (const float4*)(x + (size_t)nb * 128);
    float4* Xs4 = (float4*)Xs;
    for (int i = tid; i < 1024; i += 256) Xs4[i] = X4[i];
    __syncthreads();

    int w = tid >> 5, c = tid & 31;
    const float4* x0 = (const float4*)(Xs + (w * 4 + 0) * 128);
    const float4* x1 = (const float4*)(Xs + (w * 4 + 1) * 128);
    const float4* x2 = (const float4*)(Xs + (w * 4 + 2) * 128);
    const float4* x3 = (const float4*)(Xs + (w * 4 + 3) * 128);
    float a0 = 0.f, a1 = 0.f, a2 = 0.f, a3 = 0.f;
#pragma unroll 8
    for (int k4 = 0; k4 < 32; k4++) {
        float w0 = Ws[(4 * k4 + 0) * 32 + c];
        float w1 = Ws[(4 * k4 + 1) * 32 + c];
        float w2 = Ws[(4 * k4 + 2) * 32 + c];
        float w3 = Ws[(4 * k4 + 3) * 32 + c];
        float4 v0 = x0[k4], v1 = x1[k4], v2 = x2[k4], v3 = x3[k4];
        a0 += v0.x * w0 + v0.y * w1 + v0.z * w2 + v0.w * w3;
        a1 += v1.x * w0 + v1.y * w1 + v1.z * w2 + v1.w * w3;
        a2 += v2.x * w0 + v2.y * w1 + v2.z * w2 + v2.w * w3;
        a3 += v3.x * w0 + v3.y * w1 + v3.z * w2 + v3.w * w3;
    }
    int n0 = nb + w * 4;
    g[(size_t)(n0 + 0) * 32 + c] = a0;
    g[(size_t)(n0 + 1) * 32 + c] = a1;
    g[(size_t)(n0 + 2) * 32 + c] = a2;
    g[(size_t)(n0 + 3) * 32 + c] = a3;
}

// helpers
__device__ __forceinline__ void f4shfl_xor_add(float4& a, int m) {
    a.x += __shfl_xor_sync(0xffffffffu, a.x, m);
    a.y += __shfl_xor_sync(0xffffffffu, a.y, m);
    a.z += __shfl_xor_sync(0xffffffffu, a.z, m);
    a.w += __shfl_xor_sync(0xffffffffu, a.w, m);
}
__device__ __forceinline__ void f4add_h4(float4& a, const __half* p) {
    uint2 u = *(const uint2*)p;
    float2 f0 = __half22float2(*(const __half2*)&u.x);
    float2 f1 = __half22float2(*(const __half2*)&u.y);
    a.x += f0.x; a.y += f0.y; a.z += f1.x; a.w += f1.y;
}
// flush half2 partials into fp32 accumulator and reset them
__device__ __forceinline__ void flush2(float4& a, __half2& p0, __half2& p1) {
    float2 f0 = __half22float2(p0);
    float2 f1 = __half22float2(p1);
    a.x += f0.x; a.y += f0.y; a.z += f1.x; a.w += f1.y;
    p0 = __half2half2(__float2half(0.f));
    p1 = __half2half2(__float2half(0.f));
}

// ---- agg1 + fused gemm2 (h1 fp16, pre-scaled by dinv) ----
// warp per node; 4 edge-groups x 8 channel-quads; half2 accumulate, flush/4 chunks.
__global__ void k_agg1_gemm2(const float* __restrict__ b1,
                             const float* __restrict__ W2) {
    __shared__ float W2s[32 * 16];
    __shared__ float Hs[8][32];
    for (int i = threadIdx.x; i < 512; i += blockDim.x) W2s[i] = W2[i];
    __syncthreads();
    int wip = threadIdx.x >> 5;
    int node = (int)((blockIdx.x * blockDim.x + threadIdx.x) >> 5);
    int lane = threadIdx.x & 31;
    if (node >= N_NODES) return;
    int grp = lane >> 3, q = lane & 7;                  // channels 4q..4q+3
    int deg = min(g_cnt[node], CAP);
    const int* row = g_bucket + (size_t)node * CAP;
    float4 acc = make_float4(0.f, 0.f, 0.f, 0.f);
    __half2 p0 = __half2half2(__float2half(0.f));
    __half2 p1 = p0;
    int nch = deg >> 2;
    int c = 0;
    for (; c + 4 <= nch; c += 4) {                      // 4 chunks = 16 edges
#pragma unroll
        for (int j = 0; j < 4; j++) {
            int src = __ldg(row + 4 * (c + j) + grp);
            uint2 u = *(const uint2*)(g_h1 + (((unsigned)src << 5) + 4u * q));
            p0 = __hadd2(p0, *(const __half2*)&u.x);
            p1 = __hadd2(p1, *(const __half2*)&u.y);
        }
        flush2(acc, p0, p1);
    }
    for (; c < nch; c++) {                              // remaining chunks (<4)
        int src = __ldg(row + 4 * c + grp);
        uint2 u = *(const uint2*)(g_h1 + (((unsigned)src << 5) + 4u * q));
        p0 = __hadd2(p0, *(const __half2*)&u.x);
        p1 = __hadd2(p1, *(const __half2*)&u.y);
    }
    for (int i = nch * 4 + grp; i < deg; i += 4) {      // tail (<4 edges)
        int src = __ldg(row + i);
        uint2 u = *(const uint2*)(g_h1 + (((unsigned)src << 5) + 4u * q));
        p0 = __hadd2(p0, *(const __half2*)&u.x);
        p1 = __hadd2(p1, *(const __half2*)&u.y);
    }
    flush2(acc, p0, p1);
    f4shfl_xor_add(acc, 8);                             // reduce 4 groups
    f4shfl_xor_add(acc, 16);

    float dn = g_dinv[node];
    if (lane < 8) {                                     // q == lane here
        float4 self = make_float4(0.f, 0.f, 0.f, 0.f);
        f4add_h4(self, g_h1 + (((unsigned)node << 5) + 4u * lane));
        float4 bb = *(const float4*)(b1 + 4 * lane);
        float4 h;
        h.x = fmaxf((acc.x + self.x) * dn + bb.x, 0.f);
        h.y = fmaxf((acc.y + self.y) * dn + bb.y, 0.f);
        h.z = fmaxf((acc.z + self.z) * dn + bb.z, 0.f);
        h.w = fmaxf((acc.w + self.w) * dn + bb.w, 0.f);
        *(float4*)(&Hs[wip][4 * lane]) = h;
    }
    __syncwarp();

    // fused 32->16 GEMM: low half lanes do k 0..15, high half k 16..31
    float o = 0.f;
    int cp = lane & 15;
    int base = (lane >= 16) ? 16 : 0;
#pragma unroll
    for (int t = 0; t < 16; t++) {
        int k = t + base;
        o += Hs[wip][k] * W2s[k * 16 + cp];
    }
    o += __shfl_xor_sync(0xffffffffu, o, 16);
    if (lane < 16) g_h2[(size_t)node * 16 + lane] = __float2half(o * dn);
}

// ---- agg2 + fused gemm3 (h2 fp16); g3 out fp32 ----
// warp per node; 8 edge-groups x 4 channel-quads; half2 accumulate, flush/4 chunks.
__global__ void k_agg2_gemm3(const float* __restrict__ b2,
                             const float* __restrict__ W3, float* __restrict__ g3) {
    __shared__ float W3s[16 * 8];
    __shared__ float Hs[8][16];
    for (int i = threadIdx.x; i < 128; i += blockDim.x) W3s[i] = W3[i];
    __syncthreads();
    int wip = threadIdx.x >> 5;
    int node = (int)((blockIdx.x * blockDim.x + threadIdx.x) >> 5);
    int lane = threadIdx.x & 31;
    if (node >= N_NODES) return;
    int grp = lane >> 2, q = lane & 3;                  // channels 4q..4q+3 of 16
    int deg = min(g_cnt[node], CAP);
    const int* row = g_bucket + (size_t)node * CAP;
    float4 acc = make_float4(0.f, 0.f, 0.f, 0.f);
    __half2 p0 = __half2half2(__float2half(0.f));
    __half2 p1 = p0;
    int nch = deg >> 3;
    int c = 0;
    for (; c + 4 <= nch; c += 4) {                      // 4 chunks = 32 edges
#pragma unroll
        for (int j = 0; j < 4; j++) {
            int src = __ldg(row + 8 * (c + j) + grp);
            uint2 u = *(const uint2*)(g_h2 + (((unsigned)src << 4) + 4u * q));
            p0 = __hadd2(p0, *(const __half2*)&u.x);
            p1 = __hadd2(p1, *(const __half2*)&u.y);
        }
        flush2(acc, p0, p1);
    }
    for (; c < nch; c++) {
        int src = __ldg(row + 8 * c + grp);
        uint2 u = *(const uint2*)(g_h2 + (((unsigned)src << 4) + 4u * q));
        p0 = __hadd2(p0, *(const __half2*)&u.x);
        p1 = __hadd2(p1, *(const __half2*)&u.y);
    }
    for (int i = nch * 8 + grp; i < deg; i += 8) {      // tail (<8 edges)
        int src = __ldg(row + i);
        uint2 u = *(const uint2*)(g_h2 + (((unsigned)src << 4) + 4u * q));
        p0 = __hadd2(p0, *(const __half2*)&u.x);
        p1 = __hadd2(p1, *(const __half2*)&u.y);
    }
    flush2(acc, p0, p1);
    f4shfl_xor_add(acc, 4);                             // reduce 8 groups
    f4shfl_xor_add(acc, 8);
    f4shfl_xor_add(acc, 16);

    float dn = g_dinv[node];
    if (lane < 4) {                                     // q == lane
        float4 self = make_float4(0.f, 0.f, 0.f, 0.f);
        f4add_h4(self, g_h2 + (((unsigned)node << 4) + 4u * lane));
        float4 bb = *(const float4*)(b2 + 4 * lane);
        float4 h;
        h.x = fmaxf((acc.x + self.x) * dn + bb.x, 0.f);
        h.y = fmaxf((acc.y + self.y) * dn + bb.y, 0.f);
        h.z = fmaxf((acc.z + self.z) * dn + bb.z, 0.f);
        h.w = fmaxf((acc.w + self.w) * dn + bb.w, 0.f);
        *(float4*)(&Hs[wip][4 * lane]) = h;
    }
    __syncwarp();

    // fused 16->8 GEMM: low half lanes do k 0..7, high half k 8..15
    float o = 0.f;
    int cp = lane & 7;
    int base = (lane >= 16) ? 8 : 0;
#pragma unroll
    for (int t = 0; t < 8; t++) {
        int k = t + base;
        o += Hs[wip][k] * W3s[k * 8 + cp];
    }
    o += __shfl_xor_sync(0xffffffffu, o, 16);
    if (lane < 8) g3[(size_t)node * 8 + lane] = o * dn;
}

// ---- final aggregate, D=8 fp32, no relu, bias b3; zeroes g_cnt for next replay ----
__global__ void k_agg3(const float* __restrict__ g, const float* __restrict__ bias,
                       float* __restrict__ out) {
    int node = (int)((blockIdx.x * blockDim.x + threadIdx.x) >> 5);
    int lane = threadIdx.x & 31;
    if (node >= N_NODES) return;
    int grp = lane >> 1, q = lane & 1;                  // channels 4q..4q+3 of 8
    int deg = min(g_cnt[node], CAP);
    const int* row = g_bucket + (size_t)node * CAP;
    float4 acc = make_float4(0.f, 0.f, 0.f, 0.f);
    int nchunk = deg >> 4;
    for (int c = 0; c < nchunk; c++) {
        int src = __ldg(row + 16 * c + grp);
        float4 v = *(const float4*)(g + (size_t)src * 8 + 4 * q);
        acc.x += v.x; acc.y += v.y; acc.z += v.z; acc.w += v.w;
    }
    for (int i = nchunk * 16 + grp; i < deg; i += 16) { // tail (<16 edges)
        int src = __ldg(row + i);
        float4 v = *(const float4*)(g + (size_t)src * 8 + 4 * q);
        acc.x += v.x; acc.y += v.y; acc.z += v.z; acc.w += v.w;
    }
    f4shfl_xor_add(acc, 2);                             // reduce 16 groups
    f4shfl_xor_add(acc, 4);
    f4shfl_xor_add(acc, 8);
    f4shfl_xor_add(acc, 16);

    if (lane < 2) {                                     // q == lane
        float dn = g_dinv[node];
        float4 self = *(const float4*)(g + (size_t)node * 8 + 4 * lane);
        float4 bb = *(const float4*)(bias + 4 * lane);
        float4 r;
        r.x = (acc.x + self.x) * dn + bb.x;
        r.y = (acc.y + self.y) * dn + bb.y;
        r.z = (acc.z + self.z) * dn + bb.z;
        r.w = (acc.w + self.w) * dn + bb.w;
        *(float4*)(out + (size_t)node * 8 + 4 * lane) = r;
    }
    if (lane == 0) g_cnt[node] = 0;                     // reset for next graph replay
}

extern "C" void kernel_launch(void* const* d_in, const int* in_sizes, int n_in,
                              void* d_out, int out_size) {
    const float* x  = (const float*)d_in[0];
    const int*   ei = (const int*)d_in[1];
    const float* W1 = (const float*)d_in[2];
    const float* b1 = (const float*)d_in[3];
    const float* W2 = (const float*)d_in[4];
    const float* b2 = (const float*)d_in[5];
    const float* W3 = (const float*)d_in[6];
    const float* b3 = (const float*)d_in[7];
    float* out = (float*)d_out;

    float *bufA = nullptr, *bufB = nullptr;
    cudaGetSymbolAddress((void**)&bufA, g_bufA);
    cudaGetSymbolAddress((void**)&bufB, g_bufB);

    static cudaStream_t s2 = nullptr;
    static cudaEvent_t evFork = nullptr, evJoin = nullptr;
    if (!s2) {
        cudaStreamCreateWithFlags(&s2, cudaStreamNonBlocking);
        cudaEventCreateWithFlags(&evFork, cudaEventDisableTiming);
        cudaEventCreateWithFlags(&evJoin, cudaEventDisableTiming);
    }

    const int TB = 256;
    const int nbE = (N_EDGES + TB - 1) / TB;
    const int nbW = (N_NODES * 32 + TB - 1) / TB;   // warp-per-node kernels

    // fork: gemm1 (zero deps) overlaps the scatter; g_cnt is zero (init / agg3 reset)
    cudaEventRecord(evFork, 0);
    cudaStreamWaitEvent(s2, evFork, 0);
    k_gemm1<<<N_NODES / 32, 256, 0, s2>>>(x, W1, bufA);
    cudaEventRecord(evJoin, s2);

    k_scatter<<<nbE, TB>>>(ei);                     // one-pass bucketed CSR
    cudaStreamWaitEvent(0, evJoin, 0);              // join gemm1

    k_finish<<<nbW, TB>>>(bufA);                    // dinv + fp16 convert/scale

    k_agg1_gemm2<<<nbW, TB>>>(b1, W2);
    k_agg2_gemm3<<<nbW, TB>>>(b2, W3, bufB);
    k_agg3      <<<nbW, TB>>>(bufB, b3, out);
}

// round 15
// speedup vs baseline: 1.1065x; 1.1065x over previous
#include <cuda_runtime.h>
#include <cuda_fp16.h>

#define N_NODES 100000
#define N_EDGES 3200000
#define CAP     128          // per-node bucket capacity; max in-degree ~60 for this graph

// ---- persistent device scratch (no allocations allowed) ----
__device__ int   g_cnt[N_NODES];                       // degree / cursor (zeroed by agg3)
__device__ float g_dinv[N_NODES];
__device__ int   g_bucket[(size_t)N_NODES * CAP];      // padded CSR (51.2 MB)
__device__ __align__(16) float  g_bufA[(size_t)N_NODES * 32];  // raw x@W1 (fp32)
__device__ __align__(16) float  g_bufB[(size_t)N_NODES * 32];  // g3 (fp32)
__device__ __align__(16) __half g_h1[(size_t)N_NODES * 32];    // scaled layer-1 feats
__device__ __align__(16) __half g_h2[(size_t)N_NODES * 16];    // scaled layer-2 feats

// dtype check: int64 edge indices < 2^31 have all-zero high (odd) int32 words.
__device__ __forceinline__ int detect_is64(const int* ei32) {
    __shared__ int s_is64;
    if (threadIdx.x < 32) {
        int pos = 2 * (threadIdx.x * 100000) + 1;      // max 6200001 < 6400000
        unsigned m = __ballot_sync(0xffffffffu, ei32[pos] != 0);
        if (threadIdx.x == 0) s_is64 = (m == 0);
    }
    __syncthreads();
    return s_is64;
}

// ---- one-pass bucketed CSR build: p = cnt[d]++; bucket[d*CAP+p] = s ----
__global__ void k_scatter(const int* __restrict__ ei32) {
    int is64 = detect_is64(ei32);
    int e = blockIdx.x * blockDim.x + threadIdx.x;
    if (e >= N_EDGES) return;
    int s, d;
    if (is64) {
        s = ei32[2 * e];
        d = ei32[2 * (N_EDGES + e)];
    } else {
        s = ei32[e];
        d = ei32[N_EDGES + e];
    }
    s = min(max(s, 0), N_NODES - 1);
    d = min(max(d, 0), N_NODES - 1);
    int p = atomicAdd(&g_cnt[d], 1);
    if (p < CAP) g_bucket[(size_t)d * CAP + p] = s;
}

// ---- finish: dinv = rsqrt(deg+1); h1[n][c] = fp16( bufA[n][c] * dinv[n] ) ----
__global__ void k_finish(const float* __restrict__ g) {
    int node = (int)((blockIdx.x * blockDim.x + threadIdx.x) >> 5);
    int lane = threadIdx.x & 31;
    if (node >= N_NODES) return;
    float dn = rsqrtf((float)(g_cnt[node] + 1));
    if (lane == 0) g_dinv[node] = dn;
    g_h1[(size_t)node * 32 + lane] = __float2half(g[(size_t)node * 32 + lane] * dn);
}

// ---- layer-1 GEMM: 128 -> 32, raw fp32 (no deps -> overlaps scatter) ----
__global__ void k_gemm1(const float* __restrict__ x, const float* __restrict__ W,
                        float* __restrict__ g) {
    __shared__ float Xs[32 * 128];
    __shared__ float Ws[128 * 32];
    int tid = threadIdx.x;
    int nb = blockIdx.x * 32;

    const float4* W4 = (const float4*)W;
    float4* Ws4 = (float4*)Ws;
    for (int i = tid; i < 1024; i += 256) Ws4[i] = W4[i];
    const float4* X4 = (const float4*)(x + (size_t)nb * 128);
    float4* Xs4 = (float4*)Xs;
    for (int i = tid; i < 1024; i += 256) Xs4[i] = X4[i];
    __syncthreads();

    int w = tid >> 5, c = tid & 31;
    const float4* x0 = (const float4*)(Xs + (w * 4 + 0) * 128);
    const float4* x1 = (const float4*)(Xs + (w * 4 + 1) * 128);
    const float4* x2 = (const float4*)(Xs + (w * 4 + 2) * 128);
    const float4* x3 = (const float4*)(Xs + (w * 4 + 3) * 128);
    float a0 = 0.f, a1 = 0.f, a2 = 0.f, a3 = 0.f;
#pragma unroll 8
    for (int k4 = 0; k4 < 32; k4++) {
        float w0 = Ws[(4 * k4 + 0) * 32 + c];
        float w1 = Ws[(4 * k4 + 1) * 32 + c];
        float w2 = Ws[(4 * k4 + 2) * 32 + c];
        float w3 = Ws[(4 * k4 + 3) * 32 + c];
        float4 v0 = x0[k4], v1 = x1[k4], v2 = x2[k4], v3 = x3[k4];
        a0 += v0.x * w0 + v0.y * w1 + v0.z * w2 + v0.w * w3;
        a1 += v1.x * w0 + v1.y * w1 + v1.z * w2 + v1.w * w3;
        a2 += v2.x * w0 + v2.y * w1 + v2.z * w2 + v2.w * w3;
        a3 += v3.x * w0 + v3.y * w1 + v3.z * w2 + v3.w * w3;
    }
    int n0 = nb + w * 4;
    g[(size_t)(n0 + 0) * 32 + c] = a0;
    g[(size_t)(n0 + 1) * 32 + c] = a1;
    g[(size_t)(n0 + 2) * 32 + c] = a2;
    g[(size_t)(n0 + 3) * 32 + c] = a3;
}

// helpers
__device__ __forceinline__ void f4shfl_xor_add(float4& a, int m) {
    a.x += __shfl_xor_sync(0xffffffffu, a.x, m);
    a.y += __shfl_xor_sync(0xffffffffu, a.y, m);
    a.z += __shfl_xor_sync(0xffffffffu, a.z, m);
    a.w += __shfl_xor_sync(0xffffffffu, a.w, m);
}
__device__ __forceinline__ void f4add_h4(float4& a, const __half* p) {
    uint2 u = *(const uint2*)p;
    float2 f0 = __half22float2(*(const __half2*)&u.x);
    float2 f1 = __half22float2(*(const __half2*)&u.y);
    a.x += f0.x; a.y += f0.y; a.z += f1.x; a.w += f1.y;
}

// ---- agg1 + fused gemm2 (h1 fp16, pre-scaled by dinv) ----
// warp per node; 4 edge-groups x 8 channel-quads; 8B fp16 gathers. (R12 geometry)
__global__ void __launch_bounds__(256, 8)
k_agg1_gemm2(const float* __restrict__ b1, const float* __restrict__ W2) {
    __shared__ float W2s[32 * 16];
    __shared__ float Hs[8][32];
    for (int i = threadIdx.x; i < 512; i += blockDim.x) W2s[i] = W2[i];
    __syncthreads();
    int wip = threadIdx.x >> 5;
    int node = (int)((blockIdx.x * blockDim.x + threadIdx.x) >> 5);
    int lane = threadIdx.x & 31;
    if (node >= N_NODES) return;
    int grp = lane >> 3, q = lane & 7;                  // channels 4q..4q+3
    int deg = min(g_cnt[node], CAP);
    const int* row = g_bucket + (size_t)node * CAP;
    float4 acc = make_float4(0.f, 0.f, 0.f, 0.f);
    int nchunk = deg >> 2;
    for (int c = 0; c < nchunk; c++) {
        int src = __ldg(row + 4 * c + grp);
        f4add_h4(acc, g_h1 + (((unsigned)src << 5) + 4u * q));
    }
    for (int i = nchunk * 4 + grp; i < deg; i += 4)     // tail (<4 edges)
        f4add_h4(acc, g_h1 + (((unsigned)__ldg(row + i) << 5) + 4u * q));
    f4shfl_xor_add(acc, 8);                             // reduce 4 groups
    f4shfl_xor_add(acc, 16);

    float dn = g_dinv[node];
    if (lane < 8) {                                     // q == lane here
        float4 self = make_float4(0.f, 0.f, 0.f, 0.f);
        f4add_h4(self, g_h1 + (((unsigned)node << 5) + 4u * lane));
        float4 bb = *(const float4*)(b1 + 4 * lane);
        float4 h;
        h.x = fmaxf((acc.x + self.x) * dn + bb.x, 0.f);
        h.y = fmaxf((acc.y + self.y) * dn + bb.y, 0.f);
        h.z = fmaxf((acc.z + self.z) * dn + bb.z, 0.f);
        h.w = fmaxf((acc.w + self.w) * dn + bb.w, 0.f);
        *(float4*)(&Hs[wip][4 * lane]) = h;
    }
    __syncwarp();

    // fused 32->16 GEMM: low half lanes do k 0..15, high half k 16..31
    float o = 0.f;
    int cp = lane & 15;
    int base = (lane >= 16) ? 16 : 0;
#pragma unroll
    for (int t = 0; t < 16; t++) {
        int k = t + base;
        o += Hs[wip][k] * W2s[k * 16 + cp];
    }
    o += __shfl_xor_sync(0xffffffffu, o, 16);
    if (lane < 16) g_h2[(size_t)node * 16 + lane] = __float2half(o * dn);
}

// ---- agg2 + fused gemm3 (h2 fp16); g3 out fp32 ----
// warp per node; 8 edge-groups x 4 channel-quads; 8B fp16 gathers. (R12 geometry)
__global__ void __launch_bounds__(256, 8)
k_agg2_gemm3(const float* __restrict__ b2, const float* __restrict__ W3,
             float* __restrict__ g3) {
    __shared__ float W3s[16 * 8];
    __shared__ float Hs[8][16];
    for (int i = threadIdx.x; i < 128; i += blockDim.x) W3s[i] = W3[i];
    __syncthreads();
    int wip = threadIdx.x >> 5;
    int node = (int)((blockIdx.x * blockDim.x + threadIdx.x) >> 5);
    int lane = threadIdx.x & 31;
    if (node >= N_NODES) return;
    int grp = lane >> 2, q = lane & 3;                  // channels 4q..4q+3 of 16
    int deg = min(g_cnt[node], CAP);
    const int* row = g_bucket + (size_t)node * CAP;
    float4 acc = make_float4(0.f, 0.f, 0.f, 0.f);
    int nchunk = deg >> 3;
    for (int c = 0; c < nchunk; c++) {
        int src = __ldg(row + 8 * c + grp);
        f4add_h4(acc, g_h2 + (((unsigned)src << 4) + 4u * q));
    }
    for (int i = nchunk * 8 + grp; i < deg; i += 8)     // tail (<8 edges)
        f4add_h4(acc, g_h2 + (((unsigned)__ldg(row + i) << 4) + 4u * q));
    f4shfl_xor_add(acc, 4);                             // reduce 8 groups
    f4shfl_xor_add(acc, 8);
    f4shfl_xor_add(acc, 16);

    float dn = g_dinv[node];
    if (lane < 4) {                                     // q == lane
        float4 self = make_float4(0.f, 0.f, 0.f, 0.f);
        f4add_h4(self, g_h2 + (((unsigned)node << 4) + 4u * lane));
        float4 bb = *(const float4*)(b2 + 4 * lane);
        float4 h;
        h.x = fmaxf((acc.x + self.x) * dn + bb.x, 0.f);
        h.y = fmaxf((acc.y + self.y) * dn + bb.y, 0.f);
        h.z = fmaxf((acc.z + self.z) * dn + bb.z, 0.f);
        h.w = fmaxf((acc.w + self.w) * dn + bb.w, 0.f);
        *(float4*)(&Hs[wip][4 * lane]) = h;
    }
    __syncwarp();

    // fused 16->8 GEMM: low half lanes do k 0..7, high half k 8..15
    float o = 0.f;
    int cp = lane & 7;
    int base = (lane >= 16) ? 8 : 0;
#pragma unroll
    for (int t = 0; t < 8; t++) {
        int k = t + base;
        o += Hs[wip][k] * W3s[k * 8 + cp];
    }
    o += __shfl_xor_sync(0xffffffffu, o, 16);
    if (lane < 8) g3[(size_t)node * 8 + lane] = o * dn;
}

// ---- final aggregate, D=8 fp32, no relu, bias b3; zeroes g_cnt for next replay ----
__global__ void __launch_bounds__(256, 8)
k_agg3(const float* __restrict__ g, const float* __restrict__ bias,
       float* __restrict__ out) {
    int node = (int)((blockIdx.x * blockDim.x + threadIdx.x) >> 5);
    int lane = threadIdx.x & 31;
    if (node >= N_NODES) return;
    int grp = lane >> 1, q = lane & 1;                  // channels 4q..4q+3 of 8
    int deg = min(g_cnt[node], CAP);
    const int* row = g_bucket + (size_t)node * CAP;
    float4 acc = make_float4(0.f, 0.f, 0.f, 0.f);
    int nchunk = deg >> 4;
    for (int c = 0; c < nchunk; c++) {
        int src = __ldg(row + 16 * c + grp);
        float4 v = *(const float4*)(g + (size_t)src * 8 + 4 * q);
        acc.x += v.x; acc.y += v.y; acc.z += v.z; acc.w += v.w;
    }
    for (int i = nchunk * 16 + grp; i < deg; i += 16) { // tail (<16 edges)
        int src = __ldg(row + i);
        float4 v = *(const float4*)(g + (size_t)src * 8 + 4 * q);
        acc.x += v.x; acc.y += v.y; acc.z += v.z; acc.w += v.w;
    }
    f4shfl_xor_add(acc, 2);                             // reduce 16 groups
    f4shfl_xor_add(acc, 4);
    f4shfl_xor_add(acc, 8);
    f4shfl_xor_add(acc, 16);

    if (lane < 2) {                                     // q == lane
        float dn = g_dinv[node];
        float4 self = *(const float4*)(g + (size_t)node * 8 + 4 * lane);
        float4 bb = *(const float4*)(bias + 4 * lane);
        float4 r;
        r.x = (acc.x + self.x) * dn + bb.x;
        r.y = (acc.y + self.y) * dn + bb.y;
        r.z = (acc.z + self.z) * dn + bb.z;
        r.w = (acc.w + self.w) * dn + bb.w;
        *(float4*)(out + (size_t)node * 8 + 4 * lane) = r;
    }
    if (lane == 0) g_cnt[node] = 0;                     // reset for next graph replay
}

extern "C" void kernel_launch(void* const* d_in, const int* in_sizes, int n_in,
                              void* d_out, int out_size) {
    const float* x  = (const float*)d_in[0];
    const int*   ei = (const int*)d_in[1];
    const float* W1 = (const float*)d_in[2];
    const float* b1 = (const float*)d_in[3];
    const float* W2 = (const float*)d_in[4];
    const float* b2 = (const float*)d_in[5];
    const float* W3 = (const float*)d_in[6];
    const float* b3 = (const float*)d_in[7];
    float* out = (float*)d_out;

    float *bufA = nullptr, *bufB = nullptr;
    cudaGetSymbolAddress((void**)&bufA, g_bufA);
    cudaGetSymbolAddress((void**)&bufB, g_bufB);

    static cudaStream_t s2 = nullptr;
    static cudaEvent_t evFork = nullptr, evJoin = nullptr;
    if (!s2) {
        cudaStreamCreateWithFlags(&s2, cudaStreamNonBlocking);
        cudaEventCreateWithFlags(&evFork, cudaEventDisableTiming);
        cudaEventCreateWithFlags(&evJoin, cudaEventDisableTiming);
    }

    const int TB = 256;
    const int nbE = (N_EDGES + TB - 1) / TB;
    const int nbW = (N_NODES * 32 + TB - 1) / TB;   // warp-per-node kernels

    // fork: gemm1 (zero deps) overlaps the scatter; g_cnt is zero (init / agg3 reset)
    cudaEventRecord(evFork, 0);
    cudaStreamWaitEvent(s2, evFork, 0);
    k_gemm1<<<N_NODES / 32, 256, 0, s2>>>(x, W1, bufA);
    cudaEventRecord(evJoin, s2);

    k_scatter<<<nbE, TB>>>(ei);                     // one-pass bucketed CSR
    cudaStreamWaitEvent(0, evJoin, 0);              // join gemm1

    k_finish<<<nbW, TB>>>(bufA);                    // dinv + fp16 convert/scale

    k_agg1_gemm2<<<nbW, TB>>>(b1, W2);
    k_agg2_gemm3<<<nbW, TB>>>(b2, W3, bufB);
    k_agg3      <<<nbW, TB>>>(bufB, b3, out);
}

// round 16
// speedup vs baseline: 1.1419x; 1.0320x over previous
#include <cuda_runtime.h>
#include <cuda_fp16.h>

#define N_NODES 100000
#define N_EDGES 3200000
#define CAP     128          // per-node bucket capacity; max in-degree ~60 for this graph

// ---- persistent device scratch (no allocations allowed) ----
__device__ int   g_cnt[N_NODES];                       // degree / cursor
__device__ float g_dinv[N_NODES];
__device__ int   g_bucket[(size_t)N_NODES * CAP];      // padded CSR (51.2 MB)
__device__ __align__(16) float  g_bufA[(size_t)N_NODES * 32];  // raw x@W1 (fp32)
__device__ __align__(16) __half g_h1[(size_t)N_NODES * 32];    // scaled layer-1 feats
__device__ __align__(16) __half g_h2[(size_t)N_NODES * 16];    // scaled layer-2 feats
__device__ __align__(16) __half g_h3[(size_t)N_NODES * 8];     // scaled layer-3 feats

// dtype check: int64 edge indices < 2^31 have all-zero high (odd) int32 words.
__device__ __forceinline__ int detect_is64(const int* ei32) {
    __shared__ int s_is64;
    if (threadIdx.x < 32) {
        int pos = 2 * (threadIdx.x * 100000) + 1;      // max 6200001 < 6400000
        unsigned m = __ballot_sync(0xffffffffu, ei32[pos] != 0);
        if (threadIdx.x == 0) s_is64 = (m == 0);
    }
    __syncthreads();
    return s_is64;
}

// ---- one-pass bucketed CSR build: p = cnt[d]++; bucket[d*CAP+p] = s ----
__global__ void k_scatter(const int* __restrict__ ei32) {
    int is64 = detect_is64(ei32);
    int e = blockIdx.x * blockDim.x + threadIdx.x;
    if (e >= N_EDGES) return;
    int s, d;
    if (is64) {
        s = ei32[2 * e];
        d = ei32[2 * (N_EDGES + e)];
    } else {
        s = ei32[e];
        d = ei32[N_EDGES + e];
    }
    s = min(max(s, 0), N_NODES - 1);
    d = min(max(d, 0), N_NODES - 1);
    int p = atomicAdd(&g_cnt[d], 1);
    if (p < CAP) g_bucket[(size_t)d * CAP + p] = s;
}

// ---- finish: dinv = rsqrt(deg+1); h1[n][c] = fp16( bufA[n][c] * dinv[n] ) ----
__global__ void k_finish(const float* __restrict__ g) {
    int node = (int)((blockIdx.x * blockDim.x + threadIdx.x) >> 5);
    int lane = threadIdx.x & 31;
    if (node >= N_NODES) return;
    float dn = rsqrtf((float)(g_cnt[node] + 1));
    if (lane == 0) g_dinv[node] = dn;
    g_h1[(size_t)node * 32 + lane] = __float2half(g[(size_t)node * 32 + lane] * dn);
}

// ---- layer-1 GEMM: 128 -> 32, raw fp32 (no deps -> overlaps scatter) ----
__global__ void k_gemm1(const float* __restrict__ x, const float* __restrict__ W,
                        float* __restrict__ g) {
    __shared__ float Xs[32 * 128];
    __shared__ float Ws[128 * 32];
    int tid = threadIdx.x;
    int nb = blockIdx.x * 32;

    const float4* W4 = (const float4*)W;
    float4* Ws4 = (float4*)Ws;
    for (int i = tid; i < 1024; i += 256) Ws4[i] = W4[i];
    const float4* X4 = (const float4*)(x + (size_t)nb * 128);
    float4* Xs4 = (float4*)Xs;
    for (int i = tid; i < 1024; i += 256) Xs4[i] = X4[i];
    __syncthreads();

    int w = tid >> 5, c = tid & 31;
    const float4* x0 = (const float4*)(Xs + (w * 4 + 0) * 128);
    const float4* x1 = (const float4*)(Xs + (w * 4 + 1) * 128);
    const float4* x2 = (const float4*)(Xs + (w * 4 + 2) * 128);
    const float4* x3 = (const float4*)(Xs + (w * 4 + 3) * 128);
    float a0 = 0.f, a1 = 0.f, a2 = 0.f, a3 = 0.f;
#pragma unroll 8
    for (int k4 = 0; k4 < 32; k4++) {
        float w0 = Ws[(4 * k4 + 0) * 32 + c];
        float w1 = Ws[(4 * k4 + 1) * 32 + c];
        float w2 = Ws[(4 * k4 + 2) * 32 + c];
        float w3 = Ws[(4 * k4 + 3) * 32 + c];
        float4 v0 = x0[k4], v1 = x1[k4], v2 = x2[k4], v3 = x3[k4];
        a0 += v0.x * w0 + v0.y * w1 + v0.z * w2 + v0.w * w3;
        a1 += v1.x * w0 + v1.y * w1 + v1.z * w2 + v1.w * w3;
        a2 += v2.x * w0 + v2.y * w1 + v2.z * w2 + v2.w * w3;
        a3 += v3.x * w0 + v3.y * w1 + v3.z * w2 + v3.w * w3;
    }
    int n0 = nb + w * 4;
    g[(size_t)(n0 + 0) * 32 + c] = a0;
    g[(size_t)(n0 + 1) * 32 + c] = a1;
    g[(size_t)(n0 + 2) * 32 + c] = a2;
    g[(size_t)(n0 + 3) * 32 + c] = a3;
}

// helpers
__device__ __forceinline__ void f4shfl_xor_add(float4& a, int m) {
    a.x += __shfl_xor_sync(0xffffffffu, a.x, m);
    a.y += __shfl_xor_sync(0xffffffffu, a.y, m);
    a.z += __shfl_xor_sync(0xffffffffu, a.z, m);
    a.w += __shfl_xor_sync(0xffffffffu, a.w, m);
}
__device__ __forceinline__ void f4add_h4(float4& a, const __half* p) {
    uint2 u = *(const uint2*)p;
    float2 f0 = __half22float2(*(const __half2*)&u.x);
    float2 f1 = __half22float2(*(const __half2*)&u.y);
    a.x += f0.x; a.y += f0.y; a.z += f1.x; a.w += f1.y;
}

// ---- agg1 + fused gemm2 (h1 fp16, pre-scaled by dinv)  [R12 geometry] ----
// warp per node; 4 edge-groups x 8 channel-quads; 8B fp16 gathers.
__global__ void __launch_bounds__(256, 8)
k_agg1_gemm2(const float* __restrict__ b1, const float* __restrict__ W2) {
    __shared__ float W2s[32 * 16];
    __shared__ float Hs[8][32];
    for (int i = threadIdx.x; i < 512; i += blockDim.x) W2s[i] = W2[i];
    __syncthreads();
    int wip = threadIdx.x >> 5;
    int node = (int)((blockIdx.x * blockDim.x + threadIdx.x) >> 5);
    int lane = threadIdx.x & 31;
    if (node >= N_NODES) return;
    int grp = lane >> 3, q = lane & 7;                  // channels 4q..4q+3
    int deg = min(g_cnt[node], CAP);
    const int* row = g_bucket + (size_t)node * CAP;
    float4 acc = make_float4(0.f, 0.f, 0.f, 0.f);
    int nchunk = deg >> 2;
    for (int c = 0; c < nchunk; c++) {
        int src = __ldg(row + 4 * c + grp);
        f4add_h4(acc, g_h1 + (((unsigned)src << 5) + 4u * q));
    }
    for (int i = nchunk * 4 + grp; i < deg; i += 4)     // tail (<4 edges)
        f4add_h4(acc, g_h1 + (((unsigned)__ldg(row + i) << 5) + 4u * q));
    f4shfl_xor_add(acc, 8);                             // reduce 4 groups
    f4shfl_xor_add(acc, 16);

    float dn = g_dinv[node];
    if (lane < 8) {                                     // q == lane here
        float4 self = make_float4(0.f, 0.f, 0.f, 0.f);
        f4add_h4(self, g_h1 + (((unsigned)node << 5) + 4u * lane));
        float4 bb = *(const float4*)(b1 + 4 * lane);
        float4 h;
        h.x = fmaxf((acc.x + self.x) * dn + bb.x, 0.f);
        h.y = fmaxf((acc.y + self.y) * dn + bb.y, 0.f);
        h.z = fmaxf((acc.z + self.z) * dn + bb.z, 0.f);
        h.w = fmaxf((acc.w + self.w) * dn + bb.w, 0.f);
        *(float4*)(&Hs[wip][4 * lane]) = h;
    }
    __syncwarp();

    // fused 32->16 GEMM: low half lanes do k 0..15, high half k 16..31
    float o = 0.f;
    int cp = lane & 15;
    int base = (lane >= 16) ? 16 : 0;
#pragma unroll
    for (int t = 0; t < 16; t++) {
        int k = t + base;
        o += Hs[wip][k] * W2s[k * 16 + cp];
    }
    o += __shfl_xor_sync(0xffffffffu, o, 16);
    if (lane < 16) g_h2[(size_t)node * 16 + lane] = __float2half(o * dn);
}

// ---- agg2 + fused gemm3 (h2 fp16); g3 out fp16  [R12 geometry] ----
// warp per node; 8 edge-groups x 4 channel-quads; 8B fp16 gathers.
__global__ void __launch_bounds__(256, 8)
k_agg2_gemm3(const float* __restrict__ b2, const float* __restrict__ W3) {
    __shared__ float W3s[16 * 8];
    __shared__ float Hs[8][16];
    for (int i = threadIdx.x; i < 128; i += blockDim.x) W3s[i] = W3[i];
    __syncthreads();
    int wip = threadIdx.x >> 5;
    int node = (int)((blockIdx.x * blockDim.x + threadIdx.x) >> 5);
    int lane = threadIdx.x & 31;
    if (node >= N_NODES) return;
    int grp = lane >> 2, q = lane & 3;                  // channels 4q..4q+3 of 16
    int deg = min(g_cnt[node], CAP);
    const int* row = g_bucket + (size_t)node * CAP;
    float4 acc = make_float4(0.f, 0.f, 0.f, 0.f);
    int nchunk = deg >> 3;
    for (int c = 0; c < nchunk; c++) {
        int src = __ldg(row + 8 * c + grp);
        f4add_h4(acc, g_h2 + (((unsigned)src << 4) + 4u * q));
    }
    for (int i = nchunk * 8 + grp; i < deg; i += 8)     // tail (<8 edges)
        f4add_h4(acc, g_h2 + (((unsigned)__ldg(row + i) << 4) + 4u * q));
    f4shfl_xor_add(acc, 4);                             // reduce 8 groups
    f4shfl_xor_add(acc, 8);
    f4shfl_xor_add(acc, 16);

    float dn = g_dinv[node];
    if (lane < 4) {                                     // q == lane
        float4 self = make_float4(0.f, 0.f, 0.f, 0.f);
        f4add_h4(self, g_h2 + (((unsigned)node << 4) + 4u * lane));
        float4 bb = *(const float4*)(b2 + 4 * lane);
        float4 h;
        h.x = fmaxf((acc.x + self.x) * dn + bb.x, 0.f);
        h.y = fmaxf((acc.y + self.y) * dn + bb.y, 0.f);
        h.z = fmaxf((acc.z + self.z) * dn + bb.z, 0.f);
        h.w = fmaxf((acc.w + self.w) * dn + bb.w, 0.f);
        *(float4*)(&Hs[wip][4 * lane]) = h;
    }
    __syncwarp();

    // fused 16->8 GEMM: low half lanes do k 0..7, high half k 8..15
    float o = 0.f;
    int cp = lane & 7;
    int base = (lane >= 16) ? 8 : 0;
#pragma unroll
    for (int t = 0; t < 8; t++) {
        int k = t + base;
        o += Hs[wip][k] * W3s[k * 8 + cp];
    }
    o += __shfl_xor_sync(0xffffffffu, o, 16);
    if (lane < 8) g_h3[(size_t)node * 8 + lane] = __float2half(o * dn);
}

// ---- final aggregate (h3 fp16, 16B rows); out fp32  [R12 geometry] ----
// warp per node; 16 edge-groups x 2 channel-quads; 8B fp16 gathers.
__global__ void __launch_bounds__(256, 8)
k_agg3(const float* __restrict__ bias, float* __restrict__ out) {
    int node = (int)((blockIdx.x * blockDim.x + threadIdx.x) >> 5);
    int lane = threadIdx.x & 31;
    if (node >= N_NODES) return;
    int grp = lane >> 1, q = lane & 1;                  // channels 4q..4q+3 of 8
    int deg = min(g_cnt[node], CAP);
    const int* row = g_bucket + (size_t)node * CAP;
    float4 acc = make_float4(0.f, 0.f, 0.f, 0.f);
    int nchunk = deg >> 4;
    for (int c = 0; c < nchunk; c++) {
        int src = __ldg(row + 16 * c + grp);
        f4add_h4(acc, g_h3 + (((unsigned)src << 3) + 4u * q));
    }
    for (int i = nchunk * 16 + grp; i < deg; i += 16)   // tail (<16 edges)
        f4add_h4(acc, g_h3 + (((unsigned)__ldg(row + i) << 3) + 4u * q));
    f4shfl_xor_add(acc, 2);                             // reduce 16 groups
    f4shfl_xor_add(acc, 4);
    f4shfl_xor_add(acc, 8);
    f4shfl_xor_add(acc, 16);

    if (lane < 2) {                                     // q == lane
        float dn = g_dinv[node];
        float4 self = make_float4(0.f, 0.f, 0.f, 0.f);
        f4add_h4(self, g_h3 + (((unsigned)node << 3) + 4u * lane));
        float4 bb = *(const float4*)(bias + 4 * lane);
        float4 r;
        r.x = (acc.x + self.x) * dn + bb.x;
        r.y = (acc.y + self.y) * dn + bb.y;
        r.z = (acc.z + self.z) * dn + bb.z;
        r.w = (acc.w + self.w) * dn + bb.w;
        *(float4*)(out + (size_t)node * 8 + 4 * lane) = r;
    }
}

extern "C" void kernel_launch(void* const* d_in, const int* in_sizes, int n_in,
                              void* d_out, int out_size) {
    const float* x  = (const float*)d_in[0];
    const int*   ei = (const int*)d_in[1];
    const float* W1 = (const float*)d_in[2];
    const float* b1 = (const float*)d_in[3];
    const float* W2 = (const float*)d_in[4];
    const float* b2 = (const float*)d_in[5];
    const float* W3 = (const float*)d_in[6];
    const float* b3 = (const float*)d_in[7];
    float* out = (float*)d_out;

    float* bufA = nullptr;
    int* cntPtr = nullptr;
    cudaGetSymbolAddress((void**)&bufA, g_bufA);
    cudaGetSymbolAddress((void**)&cntPtr, g_cnt);

    static cudaStream_t s2 = nullptr;
    static cudaEvent_t evFork = nullptr, evJoin = nullptr;
    if (!s2) {
        cudaStreamCreateWithFlags(&s2, cudaStreamNonBlocking);
        cudaEventCreateWithFlags(&evFork, cudaEventDisableTiming);
        cudaEventCreateWithFlags(&evJoin, cudaEventDisableTiming);
    }

    const int TB = 256;
    const int nbE = (N_EDGES + TB - 1) / TB;
    const int nbW = (N_NODES * 32 + TB - 1) / TB;   // warp-per-node kernels

    cudaMemsetAsync(cntPtr, 0, N_NODES * sizeof(int));

    // fork: gemm1 (zero deps) overlaps the scatter
    cudaEventRecord(evFork, 0);
    cudaStreamWaitEvent(s2, evFork, 0);
    k_gemm1<<<N_NODES / 32, 256, 0, s2>>>(x, W1, bufA);
    cudaEventRecord(evJoin, s2);

    k_scatter<<<nbE, TB>>>(ei);                     // one-pass bucketed CSR
    cudaStreamWaitEvent(0, evJoin, 0);              // join gemm1

    k_finish<<<nbW, TB>>>(bufA);                    // dinv + fp16 convert/scale

    k_agg1_gemm2<<<nbW, TB>>>(b1, W2);
    k_agg2_gemm3<<<nbW, TB>>>(b2, W3);
    k_agg3      <<<nbW, TB>>>(b3, out);
}

// round 17
// speedup vs baseline: 1.1422x; 1.0003x over previous
#include <cuda_runtime.h>
#include <cuda_fp16.h>

#define N_NODES 100000
#define N_EDGES 3200000
#define CAP     128          // per-node bucket capacity; max in-degree ~60 for this graph

// ---- persistent device scratch (no allocations allowed) ----
__device__ int   g_cnt[N_NODES];                       // degree / cursor
__device__ float g_dinv[N_NODES];
__device__ int   g_bucket[(size_t)N_NODES * CAP];      // padded CSR (51.2 MB)
__device__ __align__(16) float  g_bufA[(size_t)N_NODES * 32];  // raw x@W1 (fp32)
__device__ __align__(16) __half g_h1[(size_t)N_NODES * 32];    // scaled layer-1 feats
__device__ __align__(16) __half g_h2[(size_t)N_NODES * 16];    // scaled layer-2 feats
__device__ __align__(16) __half g_h3[(size_t)N_NODES * 8];     // scaled layer-3 feats

// dtype check: int64 edge indices < 2^31 have all-zero high (odd) int32 words.
__device__ __forceinline__ int detect_is64(const int* ei32) {
    __shared__ int s_is64;
    if (threadIdx.x < 32) {
        int pos = 2 * (threadIdx.x * 100000) + 1;      // max 6200001 < 6400000
        unsigned m = __ballot_sync(0xffffffffu, ei32[pos] != 0);
        if (threadIdx.x == 0) s_is64 = (m == 0);
    }
    __syncthreads();
    return s_is64;
}

// ---- one-pass bucketed CSR build: p = cnt[d]++; bucket[d*CAP+p] = s ----
__global__ void k_scatter(const int* __restrict__ ei32) {
    int is64 = detect_is64(ei32);
    int e = blockIdx.x * blockDim.x + threadIdx.x;
    if (e >= N_EDGES) return;
    int s, d;
    if (is64) {
        s = ei32[2 * e];
        d = ei32[2 * (N_EDGES + e)];
    } else {
        s = ei32[e];
        d = ei32[N_EDGES + e];
    }
    s = min(max(s, 0), N_NODES - 1);
    d = min(max(d, 0), N_NODES - 1);
    int p = atomicAdd(&g_cnt[d], 1);
    if (p < CAP) g_bucket[(size_t)d * CAP + p] = s;
}

// ---- finish: dinv = rsqrt(deg+1); h1[n][c] = fp16( bufA[n][c] * dinv[n] ) ----
__global__ void k_finish(const float* __restrict__ g) {
    int node = (int)((blockIdx.x * blockDim.x + threadIdx.x) >> 5);
    int lane = threadIdx.x & 31;
    if (node >= N_NODES) return;
    float dn = rsqrtf((float)(g_cnt[node] + 1));
    if (lane == 0) g_dinv[node] = dn;
    g_h1[(size_t)node * 32 + lane] = __float2half(g[(size_t)node * 32 + lane] * dn);
}

// ---- layer-1 GEMM: 128 -> 32, raw fp32 (no deps -> overlaps scatter) ----
__global__ void k_gemm1(const float* __restrict__ x, const float* __restrict__ W,
                        float* __restrict__ g) {
    __shared__ float Xs[32 * 128];
    __shared__ float Ws[128 * 32];
    int tid = threadIdx.x;
    int nb = blockIdx.x * 32;

    const float4* W4 = (const float4*)W;
    float4* Ws4 = (float4*)Ws;
    for (int i = tid; i < 1024; i += 256) Ws4[i] = W4[i];
    const float4* X4 = (const float4*)(x + (size_t)nb * 128);
    float4* Xs4 = (float4*)Xs;
    for (int i = tid; i < 1024; i += 256) Xs4[i] = X4[i];
    __syncthreads();

    int w = tid >> 5, c = tid & 31;
    const float4* x0 = (const float4*)(Xs + (w * 4 + 0) * 128);
    const float4* x1 = (const float4*)(Xs + (w * 4 + 1) * 128);
    const float4* x2 = (const float4*)(Xs + (w * 4 + 2) * 128);
    const float4* x3 = (const float4*)(Xs + (w * 4 + 3) * 128);
    float a0 = 0.f, a1 = 0.f, a2 = 0.f, a3 = 0.f;
#pragma unroll 8
    for (int k4 = 0; k4 < 32; k4++) {
        float w0 = Ws[(4 * k4 + 0) * 32 + c];
        float w1 = Ws[(4 * k4 + 1) * 32 + c];
        float w2 = Ws[(4 * k4 + 2) * 32 + c];
        float w3 = Ws[(4 * k4 + 3) * 32 + c];
        float4 v0 = x0[k4], v1 = x1[k4], v2 = x2[k4], v3 = x3[k4];
        a0 += v0.x * w0 + v0.y * w1 + v0.z * w2 + v0.w * w3;
        a1 += v1.x * w0 + v1.y * w1 + v1.z * w2 + v1.w * w3;
        a2 += v2.x * w0 + v2.y * w1 + v2.z * w2 + v2.w * w3;
        a3 += v3.x * w0 + v3.y * w1 + v3.z * w2 + v3.w * w3;
    }
    int n0 = nb + w * 4;
    g[(size_t)(n0 + 0) * 32 + c] = a0;
    g[(size_t)(n0 + 1) * 32 + c] = a1;
    g[(size_t)(n0 + 2) * 32 + c] = a2;
    g[(size_t)(n0 + 3) * 32 + c] = a3;
}

// helpers
__device__ __forceinline__ void f4shfl_xor_add(float4& a, int m) {
    a.x += __shfl_xor_sync(0xffffffffu, a.x, m);
    a.y += __shfl_xor_sync(0xffffffffu, a.y, m);
    a.z += __shfl_xor_sync(0xffffffffu, a.z, m);
    a.w += __shfl_xor_sync(0xffffffffu, a.w, m);
}
__device__ __forceinline__ void f4add_h4(float4& a, const __half* p) {
    uint2 u = *(const uint2*)p;
    float2 f0 = __half22float2(*(const __half2*)&u.x);
    float2 f1 = __half22float2(*(const __half2*)&u.y);
    a.x += f0.x; a.y += f0.y; a.z += f1.x; a.w += f1.y;
}

// ---- agg1 + fused gemm2 (h1 fp16, pre-scaled by dinv) ----
// warp per node; 4 edge-groups x 8 channel-quads; index prefetched 1 chunk ahead.
__global__ void __launch_bounds__(256, 8)
k_agg1_gemm2(const float* __restrict__ b1, const float* __restrict__ W2) {
    __shared__ float W2s[32 * 16];
    __shared__ float Hs[8][32];
    for (int i = threadIdx.x; i < 512; i += blockDim.x) W2s[i] = W2[i];
    __syncthreads();
    int wip = threadIdx.x >> 5;
    int node = (int)((blockIdx.x * blockDim.x + threadIdx.x) >> 5);
    int lane = threadIdx.x & 31;
    if (node >= N_NODES) return;
    int grp = lane >> 3, q = lane & 7;                  // channels 4q..4q+3
    int deg = min(g_cnt[node], CAP);
    const int* row = g_bucket + (size_t)node * CAP;
    float4 acc = make_float4(0.f, 0.f, 0.f, 0.f);
    int nchunk = deg >> 2;
    int src = (nchunk > 0) ? __ldg(row + grp) : 0;
    for (int c = 0; c < nchunk; c++) {
        int nxt = (c + 1 < nchunk) ? __ldg(row + 4 * (c + 1) + grp) : 0;
        f4add_h4(acc, g_h1 + (((unsigned)src << 5) + 4u * q));
        src = nxt;
    }
    for (int i = nchunk * 4 + grp; i < deg; i += 4)     // tail (<4 edges)
        f4add_h4(acc, g_h1 + (((unsigned)__ldg(row + i) << 5) + 4u * q));
    f4shfl_xor_add(acc, 8);                             // reduce 4 groups
    f4shfl_xor_add(acc, 16);

    float dn = g_dinv[node];
    if (lane < 8) {                                     // q == lane here
        float4 self = make_float4(0.f, 0.f, 0.f, 0.f);
        f4add_h4(self, g_h1 + (((unsigned)node << 5) + 4u * lane));
        float4 bb = *(const float4*)(b1 + 4 * lane);
        float4 h;
        h.x = fmaxf((acc.x + self.x) * dn + bb.x, 0.f);
        h.y = fmaxf((acc.y + self.y) * dn + bb.y, 0.f);
        h.z = fmaxf((acc.z + self.z) * dn + bb.z, 0.f);
        h.w = fmaxf((acc.w + self.w) * dn + bb.w, 0.f);
        *(float4*)(&Hs[wip][4 * lane]) = h;
    }
    __syncwarp();

    // fused 32->16 GEMM: low half lanes do k 0..15, high half k 16..31
    float o = 0.f;
    int cp = lane & 15;
    int base = (lane >= 16) ? 16 : 0;
#pragma unroll
    for (int t = 0; t < 16; t++) {
        int k = t + base;
        o += Hs[wip][k] * W2s[k * 16 + cp];
    }
    o += __shfl_xor_sync(0xffffffffu, o, 16);
    if (lane < 16) g_h2[(size_t)node * 16 + lane] = __float2half(o * dn);
}

// ---- agg2 + fused gemm3 (h2 fp16); g3 out fp16 ----
// warp per node; 8 edge-groups x 4 channel-quads; index prefetched 1 chunk ahead.
__global__ void __launch_bounds__(256, 8)
k_agg2_gemm3(const float* __restrict__ b2, const float* __restrict__ W3) {
    __shared__ float W3s[16 * 8];
    __shared__ float Hs[8][16];
    for (int i = threadIdx.x; i < 128; i += blockDim.x) W3s[i] = W3[i];
    __syncthreads();
    int wip = threadIdx.x >> 5;
    int node = (int)((blockIdx.x * blockDim.x + threadIdx.x) >> 5);
    int lane = threadIdx.x & 31;
    if (node >= N_NODES) return;
    int grp = lane >> 2, q = lane & 3;                  // channels 4q..4q+3 of 16
    int deg = min(g_cnt[node], CAP);
    const int* row = g_bucket + (size_t)node * CAP;
    float4 acc = make_float4(0.f, 0.f, 0.f, 0.f);
    int nchunk = deg >> 3;
    int src = (nchunk > 0) ? __ldg(row + grp) : 0;
    for (int c = 0; c < nchunk; c++) {
        int nxt = (c + 1 < nchunk) ? __ldg(row + 8 * (c + 1) + grp) : 0;
        f4add_h4(acc, g_h2 + (((unsigned)src << 4) + 4u * q));
        src = nxt;
    }
    for (int i = nchunk * 8 + grp; i < deg; i += 8)     // tail (<8 edges)
        f4add_h4(acc, g_h2 + (((unsigned)__ldg(row + i) << 4) + 4u * q));
    f4shfl_xor_add(acc, 4);                             // reduce 8 groups
    f4shfl_xor_add(acc, 8);
    f4shfl_xor_add(acc, 16);

    float dn = g_dinv[node];
    if (lane < 4) {                                     // q == lane
        float4 self = make_float4(0.f, 0.f, 0.f, 0.f);
        f4add_h4(self, g_h2 + (((unsigned)node << 4) + 4u * lane));
        float4 bb = *(const float4*)(b2 + 4 * lane);
        float4 h;
        h.x = fmaxf((acc.x + self.x) * dn + bb.x, 0.f);
        h.y = fmaxf((acc.y + self.y) * dn + bb.y, 0.f);
        h.z = fmaxf((acc.z + self.z) * dn + bb.z, 0.f);
        h.w = fmaxf((acc.w + self.w) * dn + bb.w, 0.f);
        *(float4*)(&Hs[wip][4 * lane]) = h;
    }
    __syncwarp();

    // fused 16->8 GEMM: low half lanes do k 0..7, high half k 8..15
    float o = 0.f;
    int cp = lane & 7;
    int base = (lane >= 16) ? 8 : 0;
#pragma unroll
    for (int t = 0; t < 8; t++) {
        int k = t + base;
        o += Hs[wip][k] * W3s[k * 8 + cp];
    }
    o += __shfl_xor_sync(0xffffffffu, o, 16);
    if (lane < 8) g_h3[(size_t)node * 8 + lane] = __float2half(o * dn);
}

// ---- final aggregate (h3 fp16, 16B rows); out fp32 ----
// warp per node; 16 edge-groups x 2 channel-quads; index prefetched 1 chunk ahead.
__global__ void __launch_bounds__(256, 8)
k_agg3(const float* __restrict__ bias, float* __restrict__ out) {
    int node = (int)((blockIdx.x * blockDim.x + threadIdx.x) >> 5);
    int lane = threadIdx.x & 31;
    if (node >= N_NODES) return;
    int grp = lane >> 1, q = lane & 1;                  // channels 4q..4q+3 of 8
    int deg = min(g_cnt[node], CAP);
    const int* row = g_bucket + (size_t)node * CAP;
    float4 acc = make_float4(0.f, 0.f, 0.f, 0.f);
    int nchunk = deg >> 4;
    int src = (nchunk > 0) ? __ldg(row + grp) : 0;
    for (int c = 0; c < nchunk; c++) {
        int nxt = (c + 1 < nchunk) ? __ldg(row + 16 * (c + 1) + grp) : 0;
        f4add_h4(acc, g_h3 + (((unsigned)src << 3) + 4u * q));
        src = nxt;
    }
    for (int i = nchunk * 16 + grp; i < deg; i += 16)   // tail (<16 edges)
        f4add_h4(acc, g_h3 + (((unsigned)__ldg(row + i) << 3) + 4u * q));
    f4shfl_xor_add(acc, 2);                             // reduce 16 groups
    f4shfl_xor_add(acc, 4);
    f4shfl_xor_add(acc, 8);
    f4shfl_xor_add(acc, 16);

    if (lane < 2) {                                     // q == lane
        float dn = g_dinv[node];
        float4 self = make_float4(0.f, 0.f, 0.f, 0.f);
        f4add_h4(self, g_h3 + (((unsigned)node << 3) + 4u * lane));
        float4 bb = *(const float4*)(bias + 4 * lane);
        float4 r;
        r.x = (acc.x + self.x) * dn + bb.x;
        r.y = (acc.y + self.y) * dn + bb.y;
        r.z = (acc.z + self.z) * dn + bb.z;
        r.w = (acc.w + self.w) * dn + bb.w;
        *(float4*)(out + (size_t)node * 8 + 4 * lane) = r;
    }
}

extern "C" void kernel_launch(void* const* d_in, const int* in_sizes, int n_in,
                              void* d_out, int out_size) {
    const float* x  = (const float*)d_in[0];
    const int*   ei = (const int*)d_in[1];
    const float* W1 = (const float*)d_in[2];
    const float* b1 = (const float*)d_in[3];
    const float* W2 = (const float*)d_in[4];
    const float* b2 = (const float*)d_in[5];
    const float* W3 = (const float*)d_in[6];
    const float* b3 = (const float*)d_in[7];
    float* out = (float*)d_out;

    float* bufA = nullptr;
    int* cntPtr = nullptr;
    cudaGetSymbolAddress((void**)&bufA, g_bufA);
    cudaGetSymbolAddress((void**)&cntPtr, g_cnt);

    static cudaStream_t s2 = nullptr;
    static cudaEvent_t evFork = nullptr, evJoin = nullptr;
    if (!s2) {
        cudaStreamCreateWithFlags(&s2, cudaStreamNonBlocking);
        cudaEventCreateWithFlags(&evFork, cudaEventDisableTiming);
        cudaEventCreateWithFlags(&evJoin, cudaEventDisableTiming);
    }

    const int TB = 256;
    const int nbE = (N_EDGES + TB - 1) / TB;
    const int nbW = (N_NODES * 32 + TB - 1) / TB;   // warp-per-node kernels

    cudaMemsetAsync(cntPtr, 0, N_NODES * sizeof(int));

    // fork: gemm1 (zero deps) overlaps the scatter
    cudaEventRecord(evFork, 0);
    cudaStreamWaitEvent(s2, evFork, 0);
    k_gemm1<<<N_NODES / 32, 256, 0, s2>>>(x, W1, bufA);
    cudaEventRecord(evJoin, s2);

    k_scatter<<<nbE, TB>>>(ei);                     // one-pass bucketed CSR
    cudaStreamWaitEvent(0, evJoin, 0);              // join gemm1

    k_finish<<<nbW, TB>>>(bufA);                    // dinv + fp16 convert/scale

    k_agg1_gemm2<<<nbW, TB>>>(b1, W2);
    k_agg2_gemm3<<<nbW, TB>>>(b2, W3);
    k_agg3      <<<nbW, TB>>>(b3, out);
}